// round 4
// baseline (speedup 1.0000x reference)
#include <cuda_runtime.h>

#define NN 50000
#define NE 800000
#define DD 128
#define NC 10
#define NG 64

// ---------------- scratch (static device globals; no runtime alloc) --------
__device__ float g_buf0[NN * DD];   // GEMM output y = dis * (h @ W)
__device__ float g_buf1[NN * DD];   // aggregation output h' (relu)
__device__ float g_dis[NN];
__device__ int   g_deg[NN];
__device__ int   g_off[NN + 1];
__device__ int   g_cur[NN];
__device__ int   g_csr[NE];
__device__ float g_pool[NG * DD];
__device__ float g_cnt[NG];
__device__ int   g_anyodd;          // 0 => indices are int64, nonzero => int32

__device__ __forceinline__ int ld_idx(const void* p, long long i, int is64) {
    return is64 ? (int)((const long long*)p)[i] : ((const int*)p)[i];
}

__device__ __forceinline__ unsigned f2t(float x) {
    unsigned r; asm("cvt.rna.tf32.f32 %0, %1;" : "=r"(r) : "f"(x)); return r;
}

// ---------------- setup: zero deg + dtype detect (fused) --------------------
__global__ void k_init(const void* ei) {
    int i = blockIdx.x * blockDim.x + threadIdx.x;
    if (i < NN) g_deg[i] = 0;
    if (blockIdx.x == 0) {
        // int64 indices < 50000 => every odd 32-bit word is 0.
        __shared__ int sm[256];
        int any = 0;
        for (int j = threadIdx.x; j < 4096; j += 256)
            any |= ((const int*)ei)[2 * j + 1];
        sm[threadIdx.x] = any;
        __syncthreads();
        for (int s = 128; s > 0; s >>= 1) {
            if (threadIdx.x < s) sm[threadIdx.x] |= sm[threadIdx.x + s];
            __syncthreads();
        }
        if (threadIdx.x == 0) g_anyodd = sm[0];
    }
}

__global__ void k_deg(const void* ei) {
    int e = blockIdx.x * blockDim.x + threadIdx.x;
    if (e >= NE) return;
    int is64 = (g_anyodd == 0);
    int c = ld_idx(ei, (long long)NE + e, is64);
    atomicAdd(&g_deg[c], 1);
}

// single-block exclusive scan of g_deg -> g_off/g_cur ; also dis = rsqrt(deg+1)
__global__ void k_scan() {
    __shared__ int sm[1024];
    int t = threadIdx.x;
    const int SEG = (NN + 1023) / 1024;  // 49
    int s0 = t * SEG;
    int s1 = min(s0 + SEG, NN);
    int local = 0;
    for (int i = s0; i < s1; i++) local += g_deg[i];
    sm[t] = local;
    __syncthreads();
    for (int off = 1; off < 1024; off <<= 1) {
        int v = (t >= off) ? sm[t - off] : 0;
        __syncthreads();
        sm[t] += v;
        __syncthreads();
    }
    int run = sm[t] - local;  // exclusive prefix
    for (int i = s0; i < s1; i++) {
        int d = g_deg[i];
        g_off[i] = run;
        g_cur[i] = run;
        g_dis[i] = rsqrtf((float)(d + 1));  // +1 self-loop
        run += d;
    }
    if (t == 1023) g_off[NN] = sm[1023];
}

__global__ void k_scatter(const void* ei) {
    int e = blockIdx.x * blockDim.x + threadIdx.x;
    if (e >= NE) return;
    int is64 = (g_anyodd == 0);
    int r = ld_idx(ei, e, is64);
    int c = ld_idx(ei, (long long)NE + e, is64);
    int pos = atomicAdd(&g_cur[c], 1);
    g_csr[pos] = r;
}

// ---------------- TF32 tensor-core GEMM: Y = dis .* (A @ W) -----------------
// 3-term hi/lo split: a*b ~= al*bh + ah*bl + ah*bh  (fp32-class accuracy).
// Floats staged in smem; hi/lo conversion at fragment-load time (halves LDS).
// 512 threads, 16 warps in 4x4 grid, warp tile 32x32, block tile 128x128.
#define BM 128
#define BK 16

#define MMA3(ACC, A4, B2)                                                     \
    asm volatile(                                                             \
        "mma.sync.aligned.m16n8k8.row.col.f32.tf32.tf32.f32 "                 \
        "{%0,%1,%2,%3}, {%4,%5,%6,%7}, {%8,%9}, {%0,%1,%2,%3};"               \
        : "+f"(ACC[0]), "+f"(ACC[1]), "+f"(ACC[2]), "+f"(ACC[3])              \
        : "r"(A4[0]), "r"(A4[1]), "r"(A4[2]), "r"(A4[3]),                     \
          "r"(B2[0]), "r"(B2[1]));

__global__ void __launch_bounds__(512, 1) k_gemm(const float* __restrict__ x_ext,
                                                 const float* __restrict__ W,
                                                 int layer) {
    __shared__ float As[BM][20];    // [m][k], stride 20: conflict-free frag reads
    __shared__ float Bs[BK][136];   // [k][n], stride 136 (mod 32 = 8): conflict-free

    const float* __restrict__ A = (layer == 0) ? x_ext : g_buf1;
    float* __restrict__ Y = g_buf0;

    int t = threadIdx.x;
    int m0 = blockIdx.x * BM;
    int wid = t >> 5, lane = t & 31;
    int wm = (wid >> 2) * 32;   // 4 warp-rows
    int wn = (wid & 3) * 32;    // 4 warp-cols
    int gp = lane >> 2;         // groupID 0..7
    int tig = lane & 3;         // thread-in-group 0..3

    float acc[2][4][4];
#pragma unroll
    for (int i = 0; i < 2; i++)
#pragma unroll
        for (int j = 0; j < 4; j++)
#pragma unroll
            for (int q = 0; q < 4; q++) acc[i][j][q] = 0.f;

    // staging coords (1 float4 of A + 1 float4 of W per thread per chunk)
    int ar = t >> 2, ac4 = t & 3;        // A: row 0..127, k-float4 0..3
    int bkr = t >> 5, bc4 = t & 31;      // W: k-row 0..15, n-float4 0..31

    for (int k0 = 0; k0 < DD; k0 += BK) {
        int gm = m0 + ar;
        float4 va = make_float4(0.f, 0.f, 0.f, 0.f);
        if (gm < NN) va = *(const float4*)&A[(size_t)gm * DD + k0 + ac4 * 4];
        *(float4*)&As[ar][ac4 * 4] = va;
        float4 vb = *(const float4*)&W[(size_t)(k0 + bkr) * DD + bc4 * 4];
        *(float4*)&Bs[bkr][bc4 * 4] = vb;
        __syncthreads();

#pragma unroll
        for (int ks = 0; ks < 2; ks++) {
            int k8 = ks * 8;
            unsigned ah[2][4], al[2][4];
#pragma unroll
            for (int tm = 0; tm < 2; tm++) {
                int row = wm + tm * 16 + gp;
                float f0 = As[row][k8 + tig];
                float f1 = As[row + 8][k8 + tig];
                float f2 = As[row][k8 + tig + 4];
                float f3 = As[row + 8][k8 + tig + 4];
                ah[tm][0] = f2t(f0); al[tm][0] = f2t(f0 - __uint_as_float(ah[tm][0]));
                ah[tm][1] = f2t(f1); al[tm][1] = f2t(f1 - __uint_as_float(ah[tm][1]));
                ah[tm][2] = f2t(f2); al[tm][2] = f2t(f2 - __uint_as_float(ah[tm][2]));
                ah[tm][3] = f2t(f3); al[tm][3] = f2t(f3 - __uint_as_float(ah[tm][3]));
            }
#pragma unroll
            for (int tn = 0; tn < 4; tn++) {
                int col = wn + tn * 8 + gp;
                float g0 = Bs[k8 + tig][col];
                float g1 = Bs[k8 + tig + 4][col];
                unsigned bh[2], bl[2];
                bh[0] = f2t(g0); bl[0] = f2t(g0 - __uint_as_float(bh[0]));
                bh[1] = f2t(g1); bl[1] = f2t(g1 - __uint_as_float(bh[1]));
#pragma unroll
                for (int tm = 0; tm < 2; tm++) {
                    MMA3(acc[tm][tn], al[tm], bh);   // lo_a * hi_b
                    MMA3(acc[tm][tn], ah[tm], bl);   // hi_a * lo_b
                    MMA3(acc[tm][tn], ah[tm], bh);   // hi_a * hi_b
                }
            }
        }
        __syncthreads();
    }

    // epilogue: Y[m][n] = dis[m] * acc
#pragma unroll
    for (int tm = 0; tm < 2; tm++) {
        int r0 = m0 + wm + tm * 16 + gp;
        int r1 = r0 + 8;
        float d0 = (r0 < NN) ? g_dis[r0] : 0.f;
        float d1 = (r1 < NN) ? g_dis[r1] : 0.f;
#pragma unroll
        for (int tn = 0; tn < 4; tn++) {
            int col = wn + tn * 8 + 2 * tig;
            if (r0 < NN) {
                float2 o = make_float2(d0 * acc[tm][tn][0], d0 * acc[tm][tn][1]);
                *(float2*)&Y[(size_t)r0 * DD + col] = o;
            }
            if (r1 < NN) {
                float2 o = make_float2(d1 * acc[tm][tn][2], d1 * acc[tm][tn][3]);
                *(float2*)&Y[(size_t)r1 * DD + col] = o;
            }
        }
    }
}

// ---------------- aggregation: h' = relu(dis[c]*(y[c]+sum_in y[r]) + b) ----
// in = g_buf0, out = g_buf1. One warp per node; lane owns 4 floats (float4).
__global__ void __launch_bounds__(256) k_agg(const float* __restrict__ bias) {
    int w = (blockIdx.x * blockDim.x + threadIdx.x) >> 5;
    int lane = threadIdx.x & 31;
    if (w >= NN) return;
    const float4* __restrict__ yv = (const float4*)g_buf0;
    float4 a0 = yv[(size_t)w * 32 + lane];  // self-loop contribution y[c]
    float4 a1 = make_float4(0.f, 0.f, 0.f, 0.f);
    float4 a2 = make_float4(0.f, 0.f, 0.f, 0.f);
    float4 a3 = make_float4(0.f, 0.f, 0.f, 0.f);
    int p = g_off[w];
    int e2 = g_off[w + 1];
    for (; p + 3 < e2; p += 4) {
        int r0 = g_csr[p], r1 = g_csr[p + 1], r2 = g_csr[p + 2], r3 = g_csr[p + 3];
        float4 v0 = yv[(size_t)r0 * 32 + lane];
        float4 v1 = yv[(size_t)r1 * 32 + lane];
        float4 v2 = yv[(size_t)r2 * 32 + lane];
        float4 v3 = yv[(size_t)r3 * 32 + lane];
        a0.x += v0.x; a0.y += v0.y; a0.z += v0.z; a0.w += v0.w;
        a1.x += v1.x; a1.y += v1.y; a1.z += v1.z; a1.w += v1.w;
        a2.x += v2.x; a2.y += v2.y; a2.z += v2.z; a2.w += v2.w;
        a3.x += v3.x; a3.y += v3.y; a3.z += v3.z; a3.w += v3.w;
    }
    for (; p < e2; p++) {
        int r0 = g_csr[p];
        float4 v0 = yv[(size_t)r0 * 32 + lane];
        a0.x += v0.x; a0.y += v0.y; a0.z += v0.z; a0.w += v0.w;
    }
    float ds = g_dis[w];
    float4 b = ((const float4*)bias)[lane];
    float4 o;
    o.x = fmaxf(ds * ((a0.x + a1.x) + (a2.x + a3.x)) + b.x, 0.f);
    o.y = fmaxf(ds * ((a0.y + a1.y) + (a2.y + a3.y)) + b.y, 0.f);
    o.z = fmaxf(ds * ((a0.z + a1.z) + (a2.z + a3.z)) + b.z, 0.f);
    o.w = fmaxf(ds * ((a0.w + a1.w) + (a2.w + a3.w)) + b.w, 0.f);
    ((float4*)g_buf1)[(size_t)w * 32 + lane] = o;
}

// ---------------- mean pool per graph (batch is sorted; no atomics) --------
__global__ void k_pool(const void* batch) {
    int g = blockIdx.x;
    int is64 = (g_anyodd == 0);
    int lo = 0, hi = NN;
    while (lo < hi) {
        int mid = (lo + hi) >> 1;
        if (ld_idx(batch, mid, is64) < g) lo = mid + 1; else hi = mid;
    }
    int start = lo;
    hi = NN;
    while (lo < hi) {
        int mid = (lo + hi) >> 1;
        if (ld_idx(batch, mid, is64) <= g) lo = mid + 1; else hi = mid;
    }
    int end = lo;

    int d = threadIdx.x;  // 128 threads, one dim each
    const float* __restrict__ h = g_buf1;
    float s0 = 0.f, s1 = 0.f, s2 = 0.f, s3 = 0.f;
    int i = start;
    for (; i + 3 < end; i += 4) {
        s0 += h[(size_t)i * DD + d];
        s1 += h[(size_t)(i + 1) * DD + d];
        s2 += h[(size_t)(i + 2) * DD + d];
        s3 += h[(size_t)(i + 3) * DD + d];
    }
    for (; i < end; i++) s0 += h[(size_t)i * DD + d];
    g_pool[g * DD + d] = (s0 + s1) + (s2 + s3);
    if (d == 0) g_cnt[g] = (float)(end - start);
}

// ---------------- head: emb @ Wfc + bfc, log_softmax -----------------------
__global__ void k_head(const float* __restrict__ Wfc,
                       const float* __restrict__ bfc,
                       float* __restrict__ out) {
    __shared__ float lg[NG][NC];
    int t = threadIdx.x;            // 640 threads
    int g = t / NC, c = t % NC;
    if (t < NG * NC) {
        float inv = 1.f / fmaxf(g_cnt[g], 1.f);
        float acc = bfc[c];
#pragma unroll 4
        for (int d = 0; d < DD; d++)
            acc += g_pool[g * DD + d] * inv * Wfc[d * NC + c];
        lg[g][c] = acc;
    }
    __syncthreads();
    if (t < NG * NC) {
        float m = -1e30f;
#pragma unroll
        for (int k = 0; k < NC; k++) m = fmaxf(m, lg[g][k]);
        float s = 0.f;
#pragma unroll
        for (int k = 0; k < NC; k++) s += expf(lg[g][k] - m);
        out[g * NC + c] = lg[g][c] - m - logf(s);
    }
}

// ---------------- launch ----------------------------------------------------
extern "C" void kernel_launch(void* const* d_in, const int* in_sizes, int n_in,
                              void* d_out, int out_size) {
    (void)in_sizes; (void)n_in; (void)out_size;
    const float* x   = (const float*)d_in[0];
    const void*  ei  = d_in[1];
    const void*  bat = d_in[2];
    const float* W1  = (const float*)d_in[3];
    const float* b1  = (const float*)d_in[4];
    const float* W2  = (const float*)d_in[5];
    const float* b2  = (const float*)d_in[6];
    const float* Wfc = (const float*)d_in[7];
    const float* bfc = (const float*)d_in[8];
    float* out = (float*)d_out;

    k_init<<<(NN + 255) / 256, 256>>>(ei);
    k_deg<<<(NE + 255) / 256, 256>>>(ei);
    k_scan<<<1, 1024>>>();
    k_scatter<<<(NE + 255) / 256, 256>>>(ei);

    int gblocks = (NN + BM - 1) / BM;
    k_gemm<<<gblocks, 512>>>(x, W1, 0);                 // y1 -> buf0
    k_agg<<<(NN * 32 + 255) / 256, 256>>>(b1);          // h1 -> buf1
    k_gemm<<<gblocks, 512>>>(x, W2, 1);                 // y2 -> buf0 (A=buf1)
    k_agg<<<(NN * 32 + 255) / 256, 256>>>(b2);          // h2 -> buf1

    k_pool<<<NG, DD>>>(bat);
    k_head<<<1, NG * NC>>>(Wfc, bfc, out);
}

// round 6
// speedup vs baseline: 1.0071x; 1.0071x over previous
#include <cuda_runtime.h>
#include <cstdint>

#define NN 50000
#define NE 800000
#define DD 128
#define NC 10
#define NG 64

// ---------------- scratch (static device globals; no runtime alloc) --------
__device__ float g_buf0[NN * DD];   // GEMM output y = dis * (h @ W)
__device__ float g_buf1[NN * DD];   // aggregation output h' (relu)
__device__ float g_dis[NN];
__device__ int   g_deg[NN];
__device__ int   g_off[NN + 1];
__device__ int   g_cur[NN];
__device__ int   g_csr[NE];
__device__ float g_pool[NG * DD];
__device__ float g_cnt[NG];
__device__ int   g_anyodd;          // 0 => indices are int64, nonzero => int32

__device__ __forceinline__ int ld_idx(const void* p, long long i, int is64) {
    return is64 ? (int)((const long long*)p)[i] : ((const int*)p)[i];
}

// ---------------- packed f32x2 helpers (Blackwell 2x fp32 pipe) -------------
__device__ __forceinline__ unsigned long long pk2(float x, float y) {
    unsigned long long r;
    asm("mov.b64 %0, {%1, %2};" : "=l"(r) : "f"(x), "f"(y));
    return r;
}
__device__ __forceinline__ unsigned long long ffma2(unsigned long long a,
                                                    unsigned long long b,
                                                    unsigned long long c) {
    unsigned long long d;
    asm("fma.rn.f32x2 %0, %1, %2, %3;" : "=l"(d) : "l"(a), "l"(b), "l"(c));
    return d;
}
__device__ __forceinline__ void upk2(unsigned long long v, float& x, float& y) {
    asm("mov.b64 {%0, %1}, %2;" : "=f"(x), "=f"(y) : "l"(v));
}

// ---------------- setup: zero deg + dtype detect (fused) --------------------
__global__ void k_init(const void* ei) {
    int i = blockIdx.x * blockDim.x + threadIdx.x;
    if (i < NN) g_deg[i] = 0;
    if (blockIdx.x == 0) {
        // int64 indices < 50000 => every odd 32-bit word is 0.
        __shared__ int sm[256];
        int any = 0;
        for (int j = threadIdx.x; j < 4096; j += 256)
            any |= ((const int*)ei)[2 * j + 1];
        sm[threadIdx.x] = any;
        __syncthreads();
        for (int s = 128; s > 0; s >>= 1) {
            if (threadIdx.x < s) sm[threadIdx.x] |= sm[threadIdx.x + s];
            __syncthreads();
        }
        if (threadIdx.x == 0) g_anyodd = sm[0];
    }
}

__global__ void k_deg(const void* ei) {
    int e = blockIdx.x * blockDim.x + threadIdx.x;
    if (e >= NE) return;
    int is64 = (g_anyodd == 0);
    int c = ld_idx(ei, (long long)NE + e, is64);
    atomicAdd(&g_deg[c], 1);
}

// single-block exclusive scan of g_deg -> g_off/g_cur ; also dis = rsqrt(deg+1)
__global__ void k_scan() {
    __shared__ int sm[1024];
    int t = threadIdx.x;
    const int SEG = (NN + 1023) / 1024;  // 49
    int s0 = t * SEG;
    int s1 = min(s0 + SEG, NN);
    int local = 0;
    for (int i = s0; i < s1; i++) local += g_deg[i];
    sm[t] = local;
    __syncthreads();
    for (int off = 1; off < 1024; off <<= 1) {
        int v = (t >= off) ? sm[t - off] : 0;
        __syncthreads();
        sm[t] += v;
        __syncthreads();
    }
    int run = sm[t] - local;  // exclusive prefix
    for (int i = s0; i < s1; i++) {
        int d = g_deg[i];
        g_off[i] = run;
        g_cur[i] = run;
        g_dis[i] = rsqrtf((float)(d + 1));  // +1 self-loop
        run += d;
    }
    if (t == 1023) g_off[NN] = sm[1023];
}

__global__ void k_scatter(const void* ei) {
    int e = blockIdx.x * blockDim.x + threadIdx.x;
    if (e >= NE) return;
    int is64 = (g_anyodd == 0);
    int r = ld_idx(ei, e, is64);
    int c = ld_idx(ei, (long long)NE + e, is64);
    int pos = atomicAdd(&g_cur[c], 1);
    g_csr[pos] = r;
}

// ---------------- f32x2 GEMM: Y = dis .* (A @ W) ----------------------------
// Block tile 64m x 128n, 256 threads; thread computes 8m x 4n with m paired
// into f32x2 accumulators. As is [k][m] so LDS.64 yields (m, m+1) pre-packed.
// layer==0: A = x (external).  layer==1: A = g_buf1.  Output always g_buf0.
#define GM 64
__global__ void __launch_bounds__(256) k_gemm(const float* __restrict__ x_ext,
                                              const float* __restrict__ W,
                                              int layer) {
    __shared__ float As[32][GM + 2];   // [k][m], stride 66 (8B-aligned rows)
    __shared__ float Ws[32][132];      // [k][n], stride 132 (16B-aligned rows)
    const float* __restrict__ A = (layer == 0) ? x_ext : g_buf1;
    float* __restrict__ Y = g_buf0;

    int t = threadIdx.x;
    int m0 = blockIdx.x * GM;
    int tr = t >> 5;   // 0..7  (8 row-groups of 8 m)
    int tc = t & 31;   // 0..31 (32 col-groups of 4 n)

    unsigned long long acc[4][4];      // [m-pair][n]
#pragma unroll
    for (int i = 0; i < 4; i++)
#pragma unroll
        for (int n = 0; n < 4; n++) acc[i][n] = 0ull;

    for (int k0 = 0; k0 < DD; k0 += 32) {
        // stage A tile [64 m x 32 k] transposed into As[k][m]
#pragma unroll
        for (int q = 0; q < 2; q++) {
            int id = q * 256 + t;      // 0..511
            int r  = id >> 3;          // 0..63
            int kq = id & 7;           // float4 within 32-k row
            int gm = m0 + r;
            float4 v = make_float4(0.f, 0.f, 0.f, 0.f);
            if (gm < NN) v = *(const float4*)&A[(size_t)gm * DD + k0 + kq * 4];
            As[kq * 4 + 0][r] = v.x;
            As[kq * 4 + 1][r] = v.y;
            As[kq * 4 + 2][r] = v.z;
            As[kq * 4 + 3][r] = v.w;
        }
        // stage W tile [32 k x 128 n]
#pragma unroll
        for (int q = 0; q < 4; q++) {
            int id = q * 256 + t;      // 0..1023
            int kr = id >> 5;          // 0..31
            int cq = id & 31;          // 0..31
            *(float4*)&Ws[kr][cq * 4] =
                *(const float4*)&W[(size_t)(k0 + kr) * DD + cq * 4];
        }
        __syncthreads();

#pragma unroll
        for (int kk = 0; kk < 32; kk++) {
            // 4 broadcast LDS.64: (m, m+1) pairs, already packed lo/hi
            unsigned long long ap[4];
#pragma unroll
            for (int i = 0; i < 4; i++)
                ap[i] = *(const unsigned long long*)&As[kk][tr * 8 + 2 * i];
            float4 w = *(const float4*)&Ws[kk][tc * 4];
            unsigned long long wd[4];
            wd[0] = pk2(w.x, w.x);
            wd[1] = pk2(w.y, w.y);
            wd[2] = pk2(w.z, w.z);
            wd[3] = pk2(w.w, w.w);
#pragma unroll
            for (int i = 0; i < 4; i++) {
#pragma unroll
                for (int n = 0; n < 4; n++)
                    acc[i][n] = ffma2(ap[i], wd[n], acc[i][n]);
            }
        }
        __syncthreads();
    }

    // epilogue: Y[m][n] = dis[m] * acc ; pair lo->even row, hi->odd row
#pragma unroll
    for (int i = 0; i < 4; i++) {
        int r0 = m0 + tr * 8 + 2 * i;
        int r1 = r0 + 1;
        float e0[4], e1[4];
#pragma unroll
        for (int n = 0; n < 4; n++) upk2(acc[i][n], e0[n], e1[n]);
        if (r0 < NN) {
            float d0 = g_dis[r0];
            float4 o = make_float4(d0 * e0[0], d0 * e0[1], d0 * e0[2], d0 * e0[3]);
            *(float4*)&Y[(size_t)r0 * DD + tc * 4] = o;
        }
        if (r1 < NN) {
            float d1 = g_dis[r1];
            float4 o = make_float4(d1 * e1[0], d1 * e1[1], d1 * e1[2], d1 * e1[3]);
            *(float4*)&Y[(size_t)r1 * DD + tc * 4] = o;
        }
    }
}

// ---------------- aggregation: h' = relu(dis[c]*(y[c]+sum_in y[r]) + b) ----
// in = g_buf0, out = g_buf1. One warp per node; lane owns 4 floats (float4).
__global__ void __launch_bounds__(256) k_agg(const float* __restrict__ bias) {
    int w = (blockIdx.x * blockDim.x + threadIdx.x) >> 5;
    int lane = threadIdx.x & 31;
    if (w >= NN) return;
    const float4* __restrict__ yv = (const float4*)g_buf0;
    float4 a0 = yv[(size_t)w * 32 + lane];  // self-loop contribution y[c]
    float4 a1 = make_float4(0.f, 0.f, 0.f, 0.f);
    float4 a2 = make_float4(0.f, 0.f, 0.f, 0.f);
    float4 a3 = make_float4(0.f, 0.f, 0.f, 0.f);
    int p = g_off[w];
    int e2 = g_off[w + 1];
    for (; p + 3 < e2; p += 4) {
        int r0 = g_csr[p], r1 = g_csr[p + 1], r2 = g_csr[p + 2], r3 = g_csr[p + 3];
        float4 v0 = yv[(size_t)r0 * 32 + lane];
        float4 v1 = yv[(size_t)r1 * 32 + lane];
        float4 v2 = yv[(size_t)r2 * 32 + lane];
        float4 v3 = yv[(size_t)r3 * 32 + lane];
        a0.x += v0.x; a0.y += v0.y; a0.z += v0.z; a0.w += v0.w;
        a1.x += v1.x; a1.y += v1.y; a1.z += v1.z; a1.w += v1.w;
        a2.x += v2.x; a2.y += v2.y; a2.z += v2.z; a2.w += v2.w;
        a3.x += v3.x; a3.y += v3.y; a3.z += v3.z; a3.w += v3.w;
    }
    for (; p < e2; p++) {
        int r0 = g_csr[p];
        float4 v0 = yv[(size_t)r0 * 32 + lane];
        a0.x += v0.x; a0.y += v0.y; a0.z += v0.z; a0.w += v0.w;
    }
    float ds = g_dis[w];
    float4 b = ((const float4*)bias)[lane];
    float4 o;
    o.x = fmaxf(ds * ((a0.x + a1.x) + (a2.x + a3.x)) + b.x, 0.f);
    o.y = fmaxf(ds * ((a0.y + a1.y) + (a2.y + a3.y)) + b.y, 0.f);
    o.z = fmaxf(ds * ((a0.z + a1.z) + (a2.z + a3.z)) + b.z, 0.f);
    o.w = fmaxf(ds * ((a0.w + a1.w) + (a2.w + a3.w)) + b.w, 0.f);
    ((float4*)g_buf1)[(size_t)w * 32 + lane] = o;
}

// ---------------- mean pool per graph (sorted batch; 4-row ILP) ------------
__global__ void k_pool(const void* batch) {
    __shared__ float red[4][DD];
    int g = blockIdx.x;
    int is64 = (g_anyodd == 0);
    int lo = 0, hi = NN;
    while (lo < hi) {
        int mid = (lo + hi) >> 1;
        if (ld_idx(batch, mid, is64) < g) lo = mid + 1; else hi = mid;
    }
    int start = lo;
    hi = NN;
    while (lo < hi) {
        int mid = (lo + hi) >> 1;
        if (ld_idx(batch, mid, is64) <= g) lo = mid + 1; else hi = mid;
    }
    int end = lo;

    int d = threadIdx.x & 127;
    int rg = threadIdx.x >> 7;   // 0..3
    const float* __restrict__ h = g_buf1;
    float s = 0.f;
    for (int i = start + rg; i < end; i += 4) s += h[(size_t)i * DD + d];
    red[rg][d] = s;
    __syncthreads();
    if (rg == 0) {
        g_pool[g * DD + d] = (red[0][d] + red[1][d]) + (red[2][d] + red[3][d]);
        if (d == 0) g_cnt[g] = (float)(end - start);
    }
}

// ---------------- head: emb @ Wfc + bfc, log_softmax -----------------------
__global__ void k_head(const float* __restrict__ Wfc,
                       const float* __restrict__ bfc,
                       float* __restrict__ out) {
    __shared__ float lg[NG][NC];
    int t = threadIdx.x;            // 640 threads
    int g = t / NC, c = t % NC;
    if (t < NG * NC) {
        float inv = 1.f / fmaxf(g_cnt[g], 1.f);
        float acc = bfc[c];
#pragma unroll 4
        for (int d = 0; d < DD; d++)
            acc += g_pool[g * DD + d] * inv * Wfc[d * NC + c];
        lg[g][c] = acc;
    }
    __syncthreads();
    if (t < NG * NC) {
        float m = -1e30f;
#pragma unroll
        for (int k = 0; k < NC; k++) m = fmaxf(m, lg[g][k]);
        float s = 0.f;
#pragma unroll
        for (int k = 0; k < NC; k++) s += expf(lg[g][k] - m);
        out[g * NC + c] = lg[g][c] - m - logf(s);
    }
}

// ---------------- launch ----------------------------------------------------
extern "C" void kernel_launch(void* const* d_in, const int* in_sizes, int n_in,
                              void* d_out, int out_size) {
    (void)in_sizes; (void)n_in; (void)out_size;
    const float* x   = (const float*)d_in[0];
    const void*  ei  = d_in[1];
    const void*  bat = d_in[2];
    const float* W1  = (const float*)d_in[3];
    const float* b1  = (const float*)d_in[4];
    const float* W2  = (const float*)d_in[5];
    const float* b2  = (const float*)d_in[6];
    const float* Wfc = (const float*)d_in[7];
    const float* bfc = (const float*)d_in[8];
    float* out = (float*)d_out;

    k_init<<<(NN + 255) / 256, 256>>>(ei);
    k_deg<<<(NE + 255) / 256, 256>>>(ei);
    k_scan<<<1, 1024>>>();
    k_scatter<<<(NE + 255) / 256, 256>>>(ei);

    int gblocks = (NN + GM - 1) / GM;   // 782
    k_gemm<<<gblocks, 256>>>(x, W1, 0);                 // y1 -> buf0
    k_agg<<<(NN * 32 + 255) / 256, 256>>>(b1);          // h1 -> buf1
    k_gemm<<<gblocks, 256>>>(x, W2, 1);                 // y2 -> buf0 (A=buf1)
    k_agg<<<(NN * 32 + 255) / 256, 256>>>(b2);          // h2 -> buf1

    k_pool<<<NG, 512>>>(bat);
    k_head<<<1, NG * NC>>>(Wfc, bfc, out);
}

// round 8
// speedup vs baseline: 1.3519x; 1.3424x over previous
#include <cuda_runtime.h>
#include <cstdint>

#define NN 50000
#define NE 800000
#define DD 128
#define NC 10
#define NG 64
#define NB 196   // ceil(NN/256)

// ---------------- scratch (static device globals; no runtime alloc) --------
__device__ float g_buf0[NN * DD];   // GEMM output y = dis * (h @ W)
__device__ float g_buf1[NN * DD];   // aggregation output h' (relu)
__device__ float g_dis[NN];
__device__ int   g_deg[NN];
__device__ int   g_off[NN + 1];
__device__ int   g_cur[NN];
__device__ int   g_csr[NE];
__device__ int   g_bsum[NB];
__device__ int   g_boff[NB];
__device__ float g_pool[NG * DD];
__device__ float g_cnt[NG];
__device__ int   g_anyodd;          // 0 => indices are int64, nonzero => int32

__device__ __forceinline__ int ld_idx(const void* p, long long i, int is64) {
    return is64 ? (int)((const long long*)p)[i] : ((const int*)p)[i];
}

// ---------------- setup: zero deg + dtype detect (fused) --------------------
__global__ void k_init(const void* ei) {
    int i = blockIdx.x * blockDim.x + threadIdx.x;
    if (i < NN) g_deg[i] = 0;
    if (blockIdx.x == 0) {
        // int64 indices < 50000 => every odd 32-bit word is 0.
        __shared__ int sm[256];
        int any = 0;
        for (int j = threadIdx.x; j < 4096; j += 256)
            any |= ((const int*)ei)[2 * j + 1];
        sm[threadIdx.x] = any;
        __syncthreads();
        for (int s = 128; s > 0; s >>= 1) {
            if (threadIdx.x < s) sm[threadIdx.x] |= sm[threadIdx.x + s];
            __syncthreads();
        }
        if (threadIdx.x == 0) g_anyodd = sm[0];
    }
}

__global__ void k_deg(const void* ei) {
    int e = blockIdx.x * blockDim.x + threadIdx.x;
    if (e >= NE) return;
    int is64 = (g_anyodd == 0);
    int c = ld_idx(ei, (long long)NE + e, is64);
    atomicAdd(&g_deg[c], 1);
}

// ---------------- 3-stage parallel scan of g_deg ----------------------------
__global__ void k_scanA() {
    __shared__ int sm[256];
    int t = threadIdx.x;
    int i = blockIdx.x * 256 + t;
    sm[t] = (i < NN) ? g_deg[i] : 0;
    __syncthreads();
    for (int s = 128; s > 0; s >>= 1) {
        if (t < s) sm[t] += sm[t + s];
        __syncthreads();
    }
    if (t == 0) g_bsum[blockIdx.x] = sm[0];
}

__global__ void k_scanB() {
    __shared__ int sm[256];
    int t = threadIdx.x;
    int v = (t < NB) ? g_bsum[t] : 0;
    sm[t] = v;
    __syncthreads();
    for (int off = 1; off < 256; off <<= 1) {
        int u = (t >= off) ? sm[t - off] : 0;
        __syncthreads();
        sm[t] += u;
        __syncthreads();
    }
    if (t < NB) g_boff[t] = sm[t] - v;   // exclusive
}

__global__ void k_scanC() {
    __shared__ int sm[256];
    int t = threadIdx.x;
    int i = blockIdx.x * 256 + t;
    int d = (i < NN) ? g_deg[i] : 0;
    sm[t] = d;
    __syncthreads();
    for (int off = 1; off < 256; off <<= 1) {
        int u = (t >= off) ? sm[t - off] : 0;
        __syncthreads();
        sm[t] += u;
        __syncthreads();
    }
    int off = g_boff[blockIdx.x] + sm[t] - d;   // exclusive prefix
    if (i < NN) {
        g_off[i] = off;
        g_cur[i] = off;
        g_dis[i] = rsqrtf((float)(d + 1));      // +1 self-loop
    }
    if (i == NN - 1) g_off[NN] = off + d;
}

__global__ void k_scatter(const void* ei) {
    int e = blockIdx.x * blockDim.x + threadIdx.x;
    if (e >= NE) return;
    int is64 = (g_anyodd == 0);
    int r = ld_idx(ei, e, is64);
    int c = ld_idx(ei, (long long)NE + e, is64);
    int pos = atomicAdd(&g_cur[c], 1);
    g_csr[pos] = r;
}

// ---------------- FFMA GEMM: Y = dis .* (A @ W)  (R1 proven-best) -----------
// layer==0: A = x (external).  layer==1: A = g_buf1.  Output always g_buf0.
#define GM 64
__global__ void __launch_bounds__(256) k_gemm(const float* __restrict__ x_ext,
                                              const float* __restrict__ W,
                                              int layer) {
    __shared__ float Ws[32][DD];      // [k][n], rows 16B-aligned
    __shared__ float As[32][GM + 1];  // [k][m], padded
    const float* __restrict__ A = (layer == 0) ? x_ext : g_buf1;
    float* __restrict__ Y = g_buf0;

    int t = threadIdx.x;
    int m0 = blockIdx.x * GM;
    int tr = t >> 5;   // 0..7  (8 row-groups)
    int tc = t & 31;   // 0..31 (32 col-groups of 4)

    float4 acc[8];
#pragma unroll
    for (int i = 0; i < 8; i++) acc[i] = make_float4(0.f, 0.f, 0.f, 0.f);

    for (int k0 = 0; k0 < DD; k0 += 32) {
        // load A tile [64 rows x 32 k] transposed into As[k][m]
#pragma unroll
        for (int q = 0; q < 2; q++) {
            int id = q * 256 + t;      // 0..511
            int r  = id >> 3;          // 0..63
            int kq = id & 7;           // 0..7 (float4 within row)
            int gm = m0 + r;
            float4 v = make_float4(0.f, 0.f, 0.f, 0.f);
            if (gm < NN) v = *(const float4*)&A[(size_t)gm * DD + k0 + kq * 4];
            As[kq * 4 + 0][r] = v.x;
            As[kq * 4 + 1][r] = v.y;
            As[kq * 4 + 2][r] = v.z;
            As[kq * 4 + 3][r] = v.w;
        }
        // load W tile [32 k x 128 n]
#pragma unroll
        for (int q = 0; q < 4; q++) {
            int id = q * 256 + t;      // 0..1023
            int kr = id >> 5;          // 0..31
            int cq = id & 31;          // 0..31
            *(float4*)&Ws[kr][cq * 4] =
                *(const float4*)&W[(size_t)(k0 + kr) * DD + cq * 4];
        }
        __syncthreads();

#pragma unroll
        for (int kk = 0; kk < 32; kk++) {
            float4 w = *(const float4*)&Ws[kk][tc * 4];
#pragma unroll
            for (int i = 0; i < 8; i++) {
                float a = As[kk][tr * 8 + i];
                acc[i].x += a * w.x;
                acc[i].y += a * w.y;
                acc[i].z += a * w.z;
                acc[i].w += a * w.w;
            }
        }
        __syncthreads();
    }

#pragma unroll
    for (int i = 0; i < 8; i++) {
        int gm = m0 + tr * 8 + i;
        if (gm < NN) {
            float ds = g_dis[gm];
            float4 o = make_float4(ds * acc[i].x, ds * acc[i].y,
                                   ds * acc[i].z, ds * acc[i].w);
            *(float4*)&Y[(size_t)gm * DD + tc * 4] = o;
        }
    }
}

// ---------------- aggregation: h' = relu(dis[c]*(y[c]+sum_in y[r]) + b) ----
// in = g_buf0, out = g_buf1. One warp per node; lane owns 4 floats (float4).
__global__ void __launch_bounds__(256) k_agg(const float* __restrict__ bias) {
    int w = (blockIdx.x * blockDim.x + threadIdx.x) >> 5;
    int lane = threadIdx.x & 31;
    if (w >= NN) return;
    const float4* __restrict__ yv = (const float4*)g_buf0;
    float4 a0 = yv[(size_t)w * 32 + lane];  // self-loop contribution y[c]
    float4 a1 = make_float4(0.f, 0.f, 0.f, 0.f);
    float4 a2 = make_float4(0.f, 0.f, 0.f, 0.f);
    float4 a3 = make_float4(0.f, 0.f, 0.f, 0.f);
    int p = g_off[w];
    int e2 = g_off[w + 1];
    for (; p + 3 < e2; p += 4) {
        int r0 = g_csr[p], r1 = g_csr[p + 1], r2 = g_csr[p + 2], r3 = g_csr[p + 3];
        float4 v0 = yv[(size_t)r0 * 32 + lane];
        float4 v1 = yv[(size_t)r1 * 32 + lane];
        float4 v2 = yv[(size_t)r2 * 32 + lane];
        float4 v3 = yv[(size_t)r3 * 32 + lane];
        a0.x += v0.x; a0.y += v0.y; a0.z += v0.z; a0.w += v0.w;
        a1.x += v1.x; a1.y += v1.y; a1.z += v1.z; a1.w += v1.w;
        a2.x += v2.x; a2.y += v2.y; a2.z += v2.z; a2.w += v2.w;
        a3.x += v3.x; a3.y += v3.y; a3.z += v3.z; a3.w += v3.w;
    }
    for (; p < e2; p++) {
        int r0 = g_csr[p];
        float4 v0 = yv[(size_t)r0 * 32 + lane];
        a0.x += v0.x; a0.y += v0.y; a0.z += v0.z; a0.w += v0.w;
    }
    float ds = g_dis[w];
    float4 b = ((const float4*)bias)[lane];
    float4 o;
    o.x = fmaxf(ds * ((a0.x + a1.x) + (a2.x + a3.x)) + b.x, 0.f);
    o.y = fmaxf(ds * ((a0.y + a1.y) + (a2.y + a3.y)) + b.y, 0.f);
    o.z = fmaxf(ds * ((a0.z + a1.z) + (a2.z + a3.z)) + b.z, 0.f);
    o.w = fmaxf(ds * ((a0.w + a1.w) + (a2.w + a3.w)) + b.w, 0.f);
    ((float4*)g_buf1)[(size_t)w * 32 + lane] = o;
}

// ---------------- mean pool per graph (sorted batch; 4-row ILP) ------------
__global__ void k_pool(const void* batch) {
    __shared__ float red[4][DD];
    int g = blockIdx.x;
    int is64 = (g_anyodd == 0);
    int lo = 0, hi = NN;
    while (lo < hi) {
        int mid = (lo + hi) >> 1;
        if (ld_idx(batch, mid, is64) < g) lo = mid + 1; else hi = mid;
    }
    int start = lo;
    hi = NN;
    while (lo < hi) {
        int mid = (lo + hi) >> 1;
        if (ld_idx(batch, mid, is64) <= g) lo = mid + 1; else hi = mid;
    }
    int end = lo;

    int d = threadIdx.x & 127;
    int rg = threadIdx.x >> 7;   // 0..3
    const float* __restrict__ h = g_buf1;
    float s = 0.f;
    for (int i = start + rg; i < end; i += 4) s += h[(size_t)i * DD + d];
    red[rg][d] = s;
    __syncthreads();
    if (rg == 0) {
        g_pool[g * DD + d] = (red[0][d] + red[1][d]) + (red[2][d] + red[3][d]);
        if (d == 0) g_cnt[g] = (float)(end - start);
    }
}

// ---------------- head: emb @ Wfc + bfc, log_softmax -----------------------
__global__ void k_head(const float* __restrict__ Wfc,
                       const float* __restrict__ bfc,
                       float* __restrict__ out) {
    __shared__ float lg[NG][NC];
    int t = threadIdx.x;            // 640 threads
    int g = t / NC, c = t % NC;
    if (t < NG * NC) {
        float inv = 1.f / fmaxf(g_cnt[g], 1.f);
        float acc = bfc[c];
#pragma unroll 4
        for (int d = 0; d < DD; d++)
            acc += g_pool[g * DD + d] * inv * Wfc[d * NC + c];
        lg[g][c] = acc;
    }
    __syncthreads();
    if (t < NG * NC) {
        float m = -1e30f;
#pragma unroll
        for (int k = 0; k < NC; k++) m = fmaxf(m, lg[g][k]);
        float s = 0.f;
#pragma unroll
        for (int k = 0; k < NC; k++) s += expf(lg[g][k] - m);
        out[g * NC + c] = lg[g][c] - m - logf(s);
    }
}

// ---------------- launch ----------------------------------------------------
extern "C" void kernel_launch(void* const* d_in, const int* in_sizes, int n_in,
                              void* d_out, int out_size) {
    (void)in_sizes; (void)n_in; (void)out_size;
    const float* x   = (const float*)d_in[0];
    const void*  ei  = d_in[1];
    const void*  bat = d_in[2];
    const float* W1  = (const float*)d_in[3];
    const float* b1  = (const float*)d_in[4];
    const float* W2  = (const float*)d_in[5];
    const float* b2  = (const float*)d_in[6];
    const float* Wfc = (const float*)d_in[7];
    const float* bfc = (const float*)d_in[8];
    float* out = (float*)d_out;

    k_init<<<NB, 256>>>(ei);
    k_deg<<<(NE + 255) / 256, 256>>>(ei);
    k_scanA<<<NB, 256>>>();
    k_scanB<<<1, 256>>>();
    k_scanC<<<NB, 256>>>();
    k_scatter<<<(NE + 255) / 256, 256>>>(ei);

    int gblocks = (NN + GM - 1) / GM;   // 782
    k_gemm<<<gblocks, 256>>>(x, W1, 0);                 // y1 -> buf0
    k_agg<<<(NN * 32 + 255) / 256, 256>>>(b1);          // h1 -> buf1
    k_gemm<<<gblocks, 256>>>(x, W2, 1);                 // y2 -> buf0 (A=buf1)
    k_agg<<<(NN * 32 + 255) / 256, 256>>>(b2);          // h2 -> buf1

    k_pool<<<NG, 512>>>(bat);
    k_head<<<1, NG * NC>>>(Wfc, bfc, out);
}

// round 9
// speedup vs baseline: 1.4228x; 1.0524x over previous
#include <cuda_runtime.h>
#include <cstdint>

#define NN 50000
#define NE 800000
#define DD 128
#define NC 10
#define NG 64
#define NB 196   // ceil(NN/256)

// ---------------- scratch (static device globals; no runtime alloc) --------
__device__ float g_buf0[NN * DD];   // GEMM output (xw, raw or dis-scaled)
__device__ float g_buf1[NN * DD];   // aggregation output h' (relu)
__device__ float g_dis[NN];
__device__ int   g_deg[NN];
__device__ int   g_off[NN + 1];
__device__ int   g_cur[NN];
__device__ int   g_csr[NE];
__device__ int   g_bsum[NB];
__device__ int   g_boff[NB];
__device__ float g_pool[NG * DD];
__device__ float g_cnt[NG];
__device__ int   g_anyodd;          // 0 => indices are int64, nonzero => int32

__device__ __forceinline__ int ld_idx(const void* p, long long i, int is64) {
    return is64 ? (int)((const long long*)p)[i] : ((const int*)p)[i];
}

// ---------------- setup: zero deg + dtype detect (fused) --------------------
__global__ void k_init(const void* ei) {
    int i = blockIdx.x * blockDim.x + threadIdx.x;
    if (i < NN) g_deg[i] = 0;
    if (blockIdx.x == 0) {
        // int64 indices < 50000 => every odd 32-bit word is 0.
        __shared__ int sm[256];
        int any = 0;
        for (int j = threadIdx.x; j < 4096; j += 256)
            any |= ((const int*)ei)[2 * j + 1];
        sm[threadIdx.x] = any;
        __syncthreads();
        for (int s = 128; s > 0; s >>= 1) {
            if (threadIdx.x < s) sm[threadIdx.x] |= sm[threadIdx.x + s];
            __syncthreads();
        }
        if (threadIdx.x == 0) g_anyodd = sm[0];
    }
}

__global__ void k_deg(const void* ei) {
    int e = blockIdx.x * blockDim.x + threadIdx.x;
    if (e >= NE) return;
    int is64 = (g_anyodd == 0);
    int c = ld_idx(ei, (long long)NE + e, is64);
    atomicAdd(&g_deg[c], 1);
}

// ---------------- 3-stage parallel scan of g_deg ----------------------------
__global__ void k_scanA() {
    __shared__ int sm[256];
    int t = threadIdx.x;
    int i = blockIdx.x * 256 + t;
    sm[t] = (i < NN) ? g_deg[i] : 0;
    __syncthreads();
    for (int s = 128; s > 0; s >>= 1) {
        if (t < s) sm[t] += sm[t + s];
        __syncthreads();
    }
    if (t == 0) g_bsum[blockIdx.x] = sm[0];
}

__global__ void k_scanB() {
    __shared__ int sm[256];
    int t = threadIdx.x;
    int v = (t < NB) ? g_bsum[t] : 0;
    sm[t] = v;
    __syncthreads();
    for (int off = 1; off < 256; off <<= 1) {
        int u = (t >= off) ? sm[t - off] : 0;
        __syncthreads();
        sm[t] += u;
        __syncthreads();
    }
    if (t < NB) g_boff[t] = sm[t] - v;   // exclusive
}

__global__ void k_scanC() {
    __shared__ int sm[256];
    int t = threadIdx.x;
    int i = blockIdx.x * 256 + t;
    int d = (i < NN) ? g_deg[i] : 0;
    sm[t] = d;
    __syncthreads();
    for (int off = 1; off < 256; off <<= 1) {
        int u = (t >= off) ? sm[t - off] : 0;
        __syncthreads();
        sm[t] += u;
        __syncthreads();
    }
    int off = g_boff[blockIdx.x] + sm[t] - d;   // exclusive prefix
    if (i < NN) {
        g_off[i] = off;
        g_cur[i] = off;
        g_dis[i] = rsqrtf((float)(d + 1));      // +1 self-loop
    }
    if (i == NN - 1) g_off[NN] = off + d;
}

__global__ void k_scatter(const void* ei) {
    int e = blockIdx.x * blockDim.x + threadIdx.x;
    if (e >= NE) return;
    int is64 = (g_anyodd == 0);
    int r = ld_idx(ei, e, is64);
    int c = ld_idx(ei, (long long)NE + e, is64);
    int pos = atomicAdd(&g_cur[c], 1);
    g_csr[pos] = r;
}

// ---------------- FFMA GEMM (R1 proven-best) --------------------------------
// layer==0: A = x, epilogue stores RAW xw (no dis -> no setup dependency).
// layer==1: A = g_buf1, epilogue scales by dis.  Output always g_buf0.
#define GM 64
__global__ void __launch_bounds__(256) k_gemm(const float* __restrict__ x_ext,
                                              const float* __restrict__ W,
                                              int layer) {
    __shared__ float Ws[32][DD];      // [k][n], rows 16B-aligned
    __shared__ float As[32][GM + 1];  // [k][m], padded
    const float* __restrict__ A = (layer == 0) ? x_ext : g_buf1;
    float* __restrict__ Y = g_buf0;

    int t = threadIdx.x;
    int m0 = blockIdx.x * GM;
    int tr = t >> 5;   // 0..7  (8 row-groups)
    int tc = t & 31;   // 0..31 (32 col-groups of 4)

    float4 acc[8];
#pragma unroll
    for (int i = 0; i < 8; i++) acc[i] = make_float4(0.f, 0.f, 0.f, 0.f);

    for (int k0 = 0; k0 < DD; k0 += 32) {
        // load A tile [64 rows x 32 k] transposed into As[k][m]
#pragma unroll
        for (int q = 0; q < 2; q++) {
            int id = q * 256 + t;      // 0..511
            int r  = id >> 3;          // 0..63
            int kq = id & 7;           // 0..7 (float4 within row)
            int gm = m0 + r;
            float4 v = make_float4(0.f, 0.f, 0.f, 0.f);
            if (gm < NN) v = *(const float4*)&A[(size_t)gm * DD + k0 + kq * 4];
            As[kq * 4 + 0][r] = v.x;
            As[kq * 4 + 1][r] = v.y;
            As[kq * 4 + 2][r] = v.z;
            As[kq * 4 + 3][r] = v.w;
        }
        // load W tile [32 k x 128 n]
#pragma unroll
        for (int q = 0; q < 4; q++) {
            int id = q * 256 + t;      // 0..1023
            int kr = id >> 5;          // 0..31
            int cq = id & 31;          // 0..31
            *(float4*)&Ws[kr][cq * 4] =
                *(const float4*)&W[(size_t)(k0 + kr) * DD + cq * 4];
        }
        __syncthreads();

#pragma unroll
        for (int kk = 0; kk < 32; kk++) {
            float4 w = *(const float4*)&Ws[kk][tc * 4];
#pragma unroll
            for (int i = 0; i < 8; i++) {
                float a = As[kk][tr * 8 + i];
                acc[i].x += a * w.x;
                acc[i].y += a * w.y;
                acc[i].z += a * w.z;
                acc[i].w += a * w.w;
            }
        }
        __syncthreads();
    }

#pragma unroll
    for (int i = 0; i < 8; i++) {
        int gm = m0 + tr * 8 + i;
        if (gm < NN) {
            float ds = (layer == 0) ? 1.f : g_dis[gm];
            float4 o = make_float4(ds * acc[i].x, ds * acc[i].y,
                                   ds * acc[i].z, ds * acc[i].w);
            *(float4*)&Y[(size_t)gm * DD + tc * 4] = o;
        }
    }
}

// ---------------- aggregation --------------------------------------------
// mode 0 (buf0 holds raw xw):  o = relu(dis[c]*(dis[c]*y[c] + sum dis[r]*y[r]) + b)
// mode 1 (buf0 holds dis*xw):  o = relu(dis[c]*(y[c] + sum y[r]) + b)
__global__ void __launch_bounds__(256) k_agg(const float* __restrict__ bias,
                                             int mode) {
    int w = (blockIdx.x * blockDim.x + threadIdx.x) >> 5;
    int lane = threadIdx.x & 31;
    if (w >= NN) return;
    const float4* __restrict__ yv = (const float4*)g_buf0;
    float ds = g_dis[w];
    float4 a0 = yv[(size_t)w * 32 + lane];  // self-loop contribution
    if (mode == 0) { a0.x *= ds; a0.y *= ds; a0.z *= ds; a0.w *= ds; }
    float4 a1 = make_float4(0.f, 0.f, 0.f, 0.f);
    float4 a2 = make_float4(0.f, 0.f, 0.f, 0.f);
    float4 a3 = make_float4(0.f, 0.f, 0.f, 0.f);
    int p = g_off[w];
    int e2 = g_off[w + 1];
    if (mode == 0) {
        for (; p + 3 < e2; p += 4) {
            int r0 = g_csr[p], r1 = g_csr[p + 1], r2 = g_csr[p + 2], r3 = g_csr[p + 3];
            float d0 = g_dis[r0], d1 = g_dis[r1], d2 = g_dis[r2], d3 = g_dis[r3];
            float4 v0 = yv[(size_t)r0 * 32 + lane];
            float4 v1 = yv[(size_t)r1 * 32 + lane];
            float4 v2 = yv[(size_t)r2 * 32 + lane];
            float4 v3 = yv[(size_t)r3 * 32 + lane];
            a0.x += d0 * v0.x; a0.y += d0 * v0.y; a0.z += d0 * v0.z; a0.w += d0 * v0.w;
            a1.x += d1 * v1.x; a1.y += d1 * v1.y; a1.z += d1 * v1.z; a1.w += d1 * v1.w;
            a2.x += d2 * v2.x; a2.y += d2 * v2.y; a2.z += d2 * v2.z; a2.w += d2 * v2.w;
            a3.x += d3 * v3.x; a3.y += d3 * v3.y; a3.z += d3 * v3.z; a3.w += d3 * v3.w;
        }
        for (; p < e2; p++) {
            int r0 = g_csr[p];
            float d0 = g_dis[r0];
            float4 v0 = yv[(size_t)r0 * 32 + lane];
            a0.x += d0 * v0.x; a0.y += d0 * v0.y; a0.z += d0 * v0.z; a0.w += d0 * v0.w;
        }
    } else {
        for (; p + 3 < e2; p += 4) {
            int r0 = g_csr[p], r1 = g_csr[p + 1], r2 = g_csr[p + 2], r3 = g_csr[p + 3];
            float4 v0 = yv[(size_t)r0 * 32 + lane];
            float4 v1 = yv[(size_t)r1 * 32 + lane];
            float4 v2 = yv[(size_t)r2 * 32 + lane];
            float4 v3 = yv[(size_t)r3 * 32 + lane];
            a0.x += v0.x; a0.y += v0.y; a0.z += v0.z; a0.w += v0.w;
            a1.x += v1.x; a1.y += v1.y; a1.z += v1.z; a1.w += v1.w;
            a2.x += v2.x; a2.y += v2.y; a2.z += v2.z; a2.w += v2.w;
            a3.x += v3.x; a3.y += v3.y; a3.z += v3.z; a3.w += v3.w;
        }
        for (; p < e2; p++) {
            int r0 = g_csr[p];
            float4 v0 = yv[(size_t)r0 * 32 + lane];
            a0.x += v0.x; a0.y += v0.y; a0.z += v0.z; a0.w += v0.w;
        }
    }
    float4 b = ((const float4*)bias)[lane];
    float4 o;
    o.x = fmaxf(ds * ((a0.x + a1.x) + (a2.x + a3.x)) + b.x, 0.f);
    o.y = fmaxf(ds * ((a0.y + a1.y) + (a2.y + a3.y)) + b.y, 0.f);
    o.z = fmaxf(ds * ((a0.z + a1.z) + (a2.z + a3.z)) + b.z, 0.f);
    o.w = fmaxf(ds * ((a0.w + a1.w) + (a2.w + a3.w)) + b.w, 0.f);
    ((float4*)g_buf1)[(size_t)w * 32 + lane] = o;
}

// ---------------- mean pool per graph (sorted batch; 4-row ILP) ------------
__global__ void k_pool(const void* batch) {
    __shared__ float red[4][DD];
    int g = blockIdx.x;
    int is64 = (g_anyodd == 0);
    int lo = 0, hi = NN;
    while (lo < hi) {
        int mid = (lo + hi) >> 1;
        if (ld_idx(batch, mid, is64) < g) lo = mid + 1; else hi = mid;
    }
    int start = lo;
    hi = NN;
    while (lo < hi) {
        int mid = (lo + hi) >> 1;
        if (ld_idx(batch, mid, is64) <= g) lo = mid + 1; else hi = mid;
    }
    int end = lo;

    int d = threadIdx.x & 127;
    int rg = threadIdx.x >> 7;   // 0..3
    const float* __restrict__ h = g_buf1;
    float s = 0.f;
    for (int i = start + rg; i < end; i += 4) s += h[(size_t)i * DD + d];
    red[rg][d] = s;
    __syncthreads();
    if (rg == 0) {
        g_pool[g * DD + d] = (red[0][d] + red[1][d]) + (red[2][d] + red[3][d]);
        if (d == 0) g_cnt[g] = (float)(end - start);
    }
}

// ---------------- head: emb @ Wfc + bfc, log_softmax -----------------------
__global__ void k_head(const float* __restrict__ Wfc,
                       const float* __restrict__ bfc,
                       float* __restrict__ out) {
    __shared__ float lg[NG][NC];
    int t = threadIdx.x;            // 640 threads
    int g = t / NC, c = t % NC;
    if (t < NG * NC) {
        float inv = 1.f / fmaxf(g_cnt[g], 1.f);
        float acc = bfc[c];
#pragma unroll 4
        for (int d = 0; d < DD; d++)
            acc += g_pool[g * DD + d] * inv * Wfc[d * NC + c];
        lg[g][c] = acc;
    }
    __syncthreads();
    if (t < NG * NC) {
        float m = -1e30f;
#pragma unroll
        for (int k = 0; k < NC; k++) m = fmaxf(m, lg[g][k]);
        float s = 0.f;
#pragma unroll
        for (int k = 0; k < NC; k++) s += expf(lg[g][k] - m);
        out[g * NC + c] = lg[g][c] - m - logf(s);
    }
}

// ---------------- launch ----------------------------------------------------
extern "C" void kernel_launch(void* const* d_in, const int* in_sizes, int n_in,
                              void* d_out, int out_size) {
    (void)in_sizes; (void)n_in; (void)out_size;
    const float* x   = (const float*)d_in[0];
    const void*  ei  = d_in[1];
    const void*  bat = d_in[2];
    const float* W1  = (const float*)d_in[3];
    const float* b1  = (const float*)d_in[4];
    const float* W2  = (const float*)d_in[5];
    const float* b2  = (const float*)d_in[6];
    const float* Wfc = (const float*)d_in[7];
    const float* bfc = (const float*)d_in[8];
    float* out = (float*)d_out;

    // Side stream + events, created once on the (uncaptured) first call and
    // reused thereafter; the launched work is identical on every call.
    static cudaStream_t s2 = nullptr;
    static cudaEvent_t ev_fork = nullptr, ev_join = nullptr;
    if (s2 == nullptr) {
        cudaStreamCreateWithFlags(&s2, cudaStreamNonBlocking);
        cudaEventCreateWithFlags(&ev_fork, cudaEventDisableTiming);
        cudaEventCreateWithFlags(&ev_join, cudaEventDisableTiming);
    }

    int gblocks = (NN + GM - 1) / GM;   // 782

    // fork: GEMM1 (raw xw, no setup dependency) runs on s2 in parallel with
    // the CSR-build chain on the main stream.
    cudaEventRecord(ev_fork, 0);
    cudaStreamWaitEvent(s2, ev_fork, 0);
    k_gemm<<<gblocks, 256, 0, s2>>>(x, W1, 0);          // xw1 -> buf0 (raw)
    cudaEventRecord(ev_join, s2);

    k_init<<<NB, 256>>>(ei);
    k_deg<<<(NE + 255) / 256, 256>>>(ei);
    k_scanA<<<NB, 256>>>();
    k_scanB<<<1, 256>>>();
    k_scanC<<<NB, 256>>>();
    k_scatter<<<(NE + 255) / 256, 256>>>(ei);

    // join: agg1 needs CSR + dis (main stream) AND buf0 (s2)
    cudaStreamWaitEvent(0, ev_join, 0);

    k_agg<<<(NN * 32 + 255) / 256, 256>>>(b1, 0);       // h1 -> buf1
    k_gemm<<<gblocks, 256>>>(x, W2, 1);                 // dis*xw2 -> buf0
    k_agg<<<(NN * 32 + 255) / 256, 256>>>(b2, 1);       // h2 -> buf1

    k_pool<<<NG, 512>>>(bat);
    k_head<<<1, NG * NC>>>(Wfc, bfc, out);
}

// round 10
// speedup vs baseline: 1.4644x; 1.0293x over previous
#include <cuda_runtime.h>
#include <cuda_bf16.h>
#include <cstdint>

#define NN 50000
#define NE 800000
#define DD 128
#define NC 10
#define NG 64
#define NB 196   // ceil(NN/256)

// ---------------- scratch (static device globals; no runtime alloc) --------
__device__ unsigned g_bh[NN * DD / 2];  // GEMM output y as bf16x2 (8B/4 dims)
__device__ float g_buf1[NN * DD];       // aggregation output h' (relu, fp32)
__device__ float g_dis[NN];
__device__ int   g_deg[NN];
__device__ int   g_off[NN + 1];
__device__ int   g_cur[NN];
__device__ int   g_csr[NE];
__device__ int   g_bsum[NB];
__device__ int   g_boff[NB];
__device__ float g_pool[NG * DD];
__device__ float g_cnt[NG];
__device__ int   g_anyodd;          // 0 => indices are int64, nonzero => int32

__device__ __forceinline__ int ld_idx(const void* p, long long i, int is64) {
    return is64 ? (int)((const long long*)p)[i] : ((const int*)p)[i];
}
__device__ __forceinline__ unsigned pack_bf(float a, float b) {
    __nv_bfloat162 h = __floats2bfloat162_rn(a, b);
    return *(unsigned*)&h;
}
__device__ __forceinline__ float2 unpack_bf(unsigned u) {
    return __bfloat1622float2(*(__nv_bfloat162*)&u);
}

// ---------------- setup: zero deg + dtype detect (fused) --------------------
__global__ void k_init(const void* ei) {
    int i = blockIdx.x * blockDim.x + threadIdx.x;
    if (i < NN) g_deg[i] = 0;
    if (blockIdx.x == 0) {
        // int64 indices < 50000 => every odd 32-bit word is 0.
        __shared__ int sm[256];
        int any = 0;
        for (int j = threadIdx.x; j < 4096; j += 256)
            any |= ((const int*)ei)[2 * j + 1];
        sm[threadIdx.x] = any;
        __syncthreads();
        for (int s = 128; s > 0; s >>= 1) {
            if (threadIdx.x < s) sm[threadIdx.x] |= sm[threadIdx.x + s];
            __syncthreads();
        }
        if (threadIdx.x == 0) g_anyodd = sm[0];
    }
}

__global__ void k_deg(const void* ei) {
    int e = blockIdx.x * blockDim.x + threadIdx.x;
    if (e >= NE) return;
    int is64 = (g_anyodd == 0);
    int c = ld_idx(ei, (long long)NE + e, is64);
    atomicAdd(&g_deg[c], 1);
}

// ---------------- 3-stage parallel scan of g_deg ----------------------------
__global__ void k_scanA() {
    __shared__ int sm[256];
    int t = threadIdx.x;
    int i = blockIdx.x * 256 + t;
    sm[t] = (i < NN) ? g_deg[i] : 0;
    __syncthreads();
    for (int s = 128; s > 0; s >>= 1) {
        if (t < s) sm[t] += sm[t + s];
        __syncthreads();
    }
    if (t == 0) g_bsum[blockIdx.x] = sm[0];
}

__global__ void k_scanB() {
    __shared__ int sm[256];
    int t = threadIdx.x;
    int v = (t < NB) ? g_bsum[t] : 0;
    sm[t] = v;
    __syncthreads();
    for (int off = 1; off < 256; off <<= 1) {
        int u = (t >= off) ? sm[t - off] : 0;
        __syncthreads();
        sm[t] += u;
        __syncthreads();
    }
    if (t < NB) g_boff[t] = sm[t] - v;   // exclusive
}

__global__ void k_scanC() {
    __shared__ int sm[256];
    int t = threadIdx.x;
    int i = blockIdx.x * 256 + t;
    int d = (i < NN) ? g_deg[i] : 0;
    sm[t] = d;
    __syncthreads();
    for (int off = 1; off < 256; off <<= 1) {
        int u = (t >= off) ? sm[t - off] : 0;
        __syncthreads();
        sm[t] += u;
        __syncthreads();
    }
    int off = g_boff[blockIdx.x] + sm[t] - d;   // exclusive prefix
    if (i < NN) {
        g_off[i] = off;
        g_cur[i] = off;
        g_dis[i] = rsqrtf((float)(d + 1));      // +1 self-loop
    }
    if (i == NN - 1) g_off[NN] = off + d;
}

__global__ void k_scatter(const void* ei) {
    int e = blockIdx.x * blockDim.x + threadIdx.x;
    if (e >= NE) return;
    int is64 = (g_anyodd == 0);
    int r = ld_idx(ei, e, is64);
    int c = ld_idx(ei, (long long)NE + e, is64);
    int pos = atomicAdd(&g_cur[c], 1);
    g_csr[pos] = r;
}

// ---------------- FFMA GEMM (R1 proven-best), bf16 output -------------------
// layer==0: A = x, stores RAW xw as bf16 (no dis -> no setup dependency).
// layer==1: A = g_buf1, stores dis*xw as bf16.
#define GM 64
__global__ void __launch_bounds__(256) k_gemm(const float* __restrict__ x_ext,
                                              const float* __restrict__ W,
                                              int layer) {
    __shared__ float Ws[32][DD];      // [k][n], rows 16B-aligned
    __shared__ float As[32][GM + 1];  // [k][m], padded
    const float* __restrict__ A = (layer == 0) ? x_ext : g_buf1;

    int t = threadIdx.x;
    int m0 = blockIdx.x * GM;
    int tr = t >> 5;   // 0..7  (8 row-groups)
    int tc = t & 31;   // 0..31 (32 col-groups of 4)

    float4 acc[8];
#pragma unroll
    for (int i = 0; i < 8; i++) acc[i] = make_float4(0.f, 0.f, 0.f, 0.f);

    for (int k0 = 0; k0 < DD; k0 += 32) {
        // load A tile [64 rows x 32 k] transposed into As[k][m]
#pragma unroll
        for (int q = 0; q < 2; q++) {
            int id = q * 256 + t;      // 0..511
            int r  = id >> 3;          // 0..63
            int kq = id & 7;           // 0..7 (float4 within row)
            int gm = m0 + r;
            float4 v = make_float4(0.f, 0.f, 0.f, 0.f);
            if (gm < NN) v = *(const float4*)&A[(size_t)gm * DD + k0 + kq * 4];
            As[kq * 4 + 0][r] = v.x;
            As[kq * 4 + 1][r] = v.y;
            As[kq * 4 + 2][r] = v.z;
            As[kq * 4 + 3][r] = v.w;
        }
        // load W tile [32 k x 128 n]
#pragma unroll
        for (int q = 0; q < 4; q++) {
            int id = q * 256 + t;      // 0..1023
            int kr = id >> 5;          // 0..31
            int cq = id & 31;          // 0..31
            *(float4*)&Ws[kr][cq * 4] =
                *(const float4*)&W[(size_t)(k0 + kr) * DD + cq * 4];
        }
        __syncthreads();

#pragma unroll
        for (int kk = 0; kk < 32; kk++) {
            float4 w = *(const float4*)&Ws[kk][tc * 4];
#pragma unroll
            for (int i = 0; i < 8; i++) {
                float a = As[kk][tr * 8 + i];
                acc[i].x += a * w.x;
                acc[i].y += a * w.y;
                acc[i].z += a * w.z;
                acc[i].w += a * w.w;
            }
        }
        __syncthreads();
    }

#pragma unroll
    for (int i = 0; i < 8; i++) {
        int gm = m0 + tr * 8 + i;
        if (gm < NN) {
            float ds = (layer == 0) ? 1.f : g_dis[gm];
            uint2 pk;
            pk.x = pack_bf(ds * acc[i].x, ds * acc[i].y);
            pk.y = pack_bf(ds * acc[i].z, ds * acc[i].w);
            *(uint2*)&g_bh[(size_t)gm * 64 + tc * 2] = pk;
        }
    }
}

// ---------------- aggregation (bf16 gathers, fp32 accumulate) ---------------
// mode 0 (g_bh holds raw xw):  o = relu(dis[c]*(dis[c]*y[c] + sum dis[r]*y[r]) + b)
// mode 1 (g_bh holds dis*xw):  o = relu(dis[c]*(y[c] + sum y[r]) + b)
__global__ void __launch_bounds__(256) k_agg(const float* __restrict__ bias,
                                             int mode) {
    int w = (blockIdx.x * blockDim.x + threadIdx.x) >> 5;
    int lane = threadIdx.x & 31;
    if (w >= NN) return;
    float ds = g_dis[w];

    uint2 sv = *(const uint2*)&g_bh[(size_t)w * 64 + lane * 2];
    float2 s0 = unpack_bf(sv.x), s1 = unpack_bf(sv.y);
    float4 a0 = make_float4(s0.x, s0.y, s1.x, s1.y);   // self-loop term
    if (mode == 0) { a0.x *= ds; a0.y *= ds; a0.z *= ds; a0.w *= ds; }
    float4 a1 = make_float4(0.f, 0.f, 0.f, 0.f);
    float4 a2 = make_float4(0.f, 0.f, 0.f, 0.f);
    float4 a3 = make_float4(0.f, 0.f, 0.f, 0.f);

    int p = g_off[w];
    int e2 = g_off[w + 1];
    if (mode == 0) {
        for (; p + 3 < e2; p += 4) {
            int r0 = g_csr[p], r1 = g_csr[p + 1], r2 = g_csr[p + 2], r3 = g_csr[p + 3];
            float d0 = g_dis[r0], d1 = g_dis[r1], d2 = g_dis[r2], d3 = g_dis[r3];
            uint2 u0 = *(const uint2*)&g_bh[(size_t)r0 * 64 + lane * 2];
            uint2 u1 = *(const uint2*)&g_bh[(size_t)r1 * 64 + lane * 2];
            uint2 u2 = *(const uint2*)&g_bh[(size_t)r2 * 64 + lane * 2];
            uint2 u3 = *(const uint2*)&g_bh[(size_t)r3 * 64 + lane * 2];
            float2 f0a = unpack_bf(u0.x), f0b = unpack_bf(u0.y);
            float2 f1a = unpack_bf(u1.x), f1b = unpack_bf(u1.y);
            float2 f2a = unpack_bf(u2.x), f2b = unpack_bf(u2.y);
            float2 f3a = unpack_bf(u3.x), f3b = unpack_bf(u3.y);
            a0.x += d0 * f0a.x; a0.y += d0 * f0a.y; a0.z += d0 * f0b.x; a0.w += d0 * f0b.y;
            a1.x += d1 * f1a.x; a1.y += d1 * f1a.y; a1.z += d1 * f1b.x; a1.w += d1 * f1b.y;
            a2.x += d2 * f2a.x; a2.y += d2 * f2a.y; a2.z += d2 * f2b.x; a2.w += d2 * f2b.y;
            a3.x += d3 * f3a.x; a3.y += d3 * f3a.y; a3.z += d3 * f3b.x; a3.w += d3 * f3b.y;
        }
        for (; p < e2; p++) {
            int r0 = g_csr[p];
            float d0 = g_dis[r0];
            uint2 u0 = *(const uint2*)&g_bh[(size_t)r0 * 64 + lane * 2];
            float2 f0a = unpack_bf(u0.x), f0b = unpack_bf(u0.y);
            a0.x += d0 * f0a.x; a0.y += d0 * f0a.y; a0.z += d0 * f0b.x; a0.w += d0 * f0b.y;
        }
    } else {
        for (; p + 3 < e2; p += 4) {
            int r0 = g_csr[p], r1 = g_csr[p + 1], r2 = g_csr[p + 2], r3 = g_csr[p + 3];
            uint2 u0 = *(const uint2*)&g_bh[(size_t)r0 * 64 + lane * 2];
            uint2 u1 = *(const uint2*)&g_bh[(size_t)r1 * 64 + lane * 2];
            uint2 u2 = *(const uint2*)&g_bh[(size_t)r2 * 64 + lane * 2];
            uint2 u3 = *(const uint2*)&g_bh[(size_t)r3 * 64 + lane * 2];
            float2 f0a = unpack_bf(u0.x), f0b = unpack_bf(u0.y);
            float2 f1a = unpack_bf(u1.x), f1b = unpack_bf(u1.y);
            float2 f2a = unpack_bf(u2.x), f2b = unpack_bf(u2.y);
            float2 f3a = unpack_bf(u3.x), f3b = unpack_bf(u3.y);
            a0.x += f0a.x; a0.y += f0a.y; a0.z += f0b.x; a0.w += f0b.y;
            a1.x += f1a.x; a1.y += f1a.y; a1.z += f1b.x; a1.w += f1b.y;
            a2.x += f2a.x; a2.y += f2a.y; a2.z += f2b.x; a2.w += f2b.y;
            a3.x += f3a.x; a3.y += f3a.y; a3.z += f3b.x; a3.w += f3b.y;
        }
        for (; p < e2; p++) {
            int r0 = g_csr[p];
            uint2 u0 = *(const uint2*)&g_bh[(size_t)r0 * 64 + lane * 2];
            float2 f0a = unpack_bf(u0.x), f0b = unpack_bf(u0.y);
            a0.x += f0a.x; a0.y += f0a.y; a0.z += f0b.x; a0.w += f0b.y;
        }
    }
    float4 b = ((const float4*)bias)[lane];
    float4 o;
    o.x = fmaxf(ds * ((a0.x + a1.x) + (a2.x + a3.x)) + b.x, 0.f);
    o.y = fmaxf(ds * ((a0.y + a1.y) + (a2.y + a3.y)) + b.y, 0.f);
    o.z = fmaxf(ds * ((a0.z + a1.z) + (a2.z + a3.z)) + b.z, 0.f);
    o.w = fmaxf(ds * ((a0.w + a1.w) + (a2.w + a3.w)) + b.w, 0.f);
    ((float4*)g_buf1)[(size_t)w * 32 + lane] = o;
}

// ---------------- mean pool per graph (sorted batch; 4-row ILP) ------------
__global__ void k_pool(const void* batch) {
    __shared__ float red[4][DD];
    int g = blockIdx.x;
    int is64 = (g_anyodd == 0);
    int lo = 0, hi = NN;
    while (lo < hi) {
        int mid = (lo + hi) >> 1;
        if (ld_idx(batch, mid, is64) < g) lo = mid + 1; else hi = mid;
    }
    int start = lo;
    hi = NN;
    while (lo < hi) {
        int mid = (lo + hi) >> 1;
        if (ld_idx(batch, mid, is64) <= g) lo = mid + 1; else hi = mid;
    }
    int end = lo;

    int d = threadIdx.x & 127;
    int rg = threadIdx.x >> 7;   // 0..3
    const float* __restrict__ h = g_buf1;
    float s = 0.f;
    for (int i = start + rg; i < end; i += 4) s += h[(size_t)i * DD + d];
    red[rg][d] = s;
    __syncthreads();
    if (rg == 0) {
        g_pool[g * DD + d] = (red[0][d] + red[1][d]) + (red[2][d] + red[3][d]);
        if (d == 0) g_cnt[g] = (float)(end - start);
    }
}

// ---------------- head: emb @ Wfc + bfc, log_softmax -----------------------
__global__ void k_head(const float* __restrict__ Wfc,
                       const float* __restrict__ bfc,
                       float* __restrict__ out) {
    __shared__ float lg[NG][NC];
    int t = threadIdx.x;            // 640 threads
    int g = t / NC, c = t % NC;
    if (t < NG * NC) {
        float inv = 1.f / fmaxf(g_cnt[g], 1.f);
        float acc = bfc[c];
#pragma unroll 4
        for (int d = 0; d < DD; d++)
            acc += g_pool[g * DD + d] * inv * Wfc[d * NC + c];
        lg[g][c] = acc;
    }
    __syncthreads();
    if (t < NG * NC) {
        float m = -1e30f;
#pragma unroll
        for (int k = 0; k < NC; k++) m = fmaxf(m, lg[g][k]);
        float s = 0.f;
#pragma unroll
        for (int k = 0; k < NC; k++) s += expf(lg[g][k] - m);
        out[g * NC + c] = lg[g][c] - m - logf(s);
    }
}

// ---------------- launch ----------------------------------------------------
extern "C" void kernel_launch(void* const* d_in, const int* in_sizes, int n_in,
                              void* d_out, int out_size) {
    (void)in_sizes; (void)n_in; (void)out_size;
    const float* x   = (const float*)d_in[0];
    const void*  ei  = d_in[1];
    const void*  bat = d_in[2];
    const float* W1  = (const float*)d_in[3];
    const float* b1  = (const float*)d_in[4];
    const float* W2  = (const float*)d_in[5];
    const float* b2  = (const float*)d_in[6];
    const float* Wfc = (const float*)d_in[7];
    const float* bfc = (const float*)d_in[8];
    float* out = (float*)d_out;

    // Side stream + events, created once on the (uncaptured) first call and
    // reused thereafter; the launched work is identical on every call.
    static cudaStream_t s2 = nullptr;
    static cudaEvent_t ev_fork = nullptr, ev_join = nullptr;
    if (s2 == nullptr) {
        cudaStreamCreateWithFlags(&s2, cudaStreamNonBlocking);
        cudaEventCreateWithFlags(&ev_fork, cudaEventDisableTiming);
        cudaEventCreateWithFlags(&ev_join, cudaEventDisableTiming);
    }

    int gblocks = (NN + GM - 1) / GM;   // 782

    // fork: GEMM1 (raw xw, no setup dependency) runs on s2 in parallel with
    // the CSR-build chain on the main stream.
    cudaEventRecord(ev_fork, 0);
    cudaStreamWaitEvent(s2, ev_fork, 0);
    k_gemm<<<gblocks, 256, 0, s2>>>(x, W1, 0);          // xw1 -> g_bh (raw)
    cudaEventRecord(ev_join, s2);

    k_init<<<NB, 256>>>(ei);
    k_deg<<<(NE + 255) / 256, 256>>>(ei);
    k_scanA<<<NB, 256>>>();
    k_scanB<<<1, 256>>>();
    k_scanC<<<NB, 256>>>();
    k_scatter<<<(NE + 255) / 256, 256>>>(ei);

    // join: agg1 needs CSR + dis (main stream) AND g_bh (s2)
    cudaStreamWaitEvent(0, ev_join, 0);

    k_agg<<<(NN * 32 + 255) / 256, 256>>>(b1, 0);       // h1 -> buf1
    k_gemm<<<gblocks, 256>>>(x, W2, 1);                 // dis*xw2 -> g_bh
    k_agg<<<(NN * 32 + 255) / 256, 256>>>(b2, 1);       // h2 -> buf1

    k_pool<<<NG, 512>>>(bat);
    k_head<<<1, NG * NC>>>(Wfc, bfc, out);
}

// round 11
// speedup vs baseline: 1.5834x; 1.0812x over previous
#include <cuda_runtime.h>
#include <cuda_bf16.h>
#include <cstdint>

#define NN 50000
#define NE 800000
#define DD 128
#define NC 10
#define NG 64
#define NB 196   // ceil(NN/256)

// ---------------- scratch (static device globals; no runtime alloc) --------
__device__ unsigned g_bh[NN * DD / 2];  // GEMM output y as bf16x2 (8B/4 dims)
__device__ float g_buf1[NN * DD];       // aggregation output h' (relu, fp32)
__device__ float g_dis[NN];
__device__ int   g_deg[NN];
__device__ int   g_off[NN + 1];
__device__ int   g_cur[NN];
__device__ int   g_csr[NE];
__device__ int   g_bsum[NB];
__device__ int   g_boff[NB];
__device__ int   g_anyodd;          // 0 => indices are int64, nonzero => int32

__device__ __forceinline__ int ld_idx(const void* p, long long i, int is64) {
    return is64 ? (int)((const long long*)p)[i] : ((const int*)p)[i];
}
__device__ __forceinline__ unsigned pack_bf(float a, float b) {
    __nv_bfloat162 h = __floats2bfloat162_rn(a, b);
    return *(unsigned*)&h;
}
__device__ __forceinline__ float2 unpack_bf(unsigned u) {
    return __bfloat1622float2(*(__nv_bfloat162*)&u);
}

// ---------------- setup: zero deg + dtype detect (fused) --------------------
__global__ void k_init(const void* ei) {
    int i = blockIdx.x * blockDim.x + threadIdx.x;
    if (i < NN) g_deg[i] = 0;
    if (blockIdx.x == 0) {
        // int64 indices < 50000 => every odd 32-bit word is 0.
        __shared__ int sm[256];
        int any = 0;
        for (int j = threadIdx.x; j < 4096; j += 256)
            any |= ((const int*)ei)[2 * j + 1];
        sm[threadIdx.x] = any;
        __syncthreads();
        for (int s = 128; s > 0; s >>= 1) {
            if (threadIdx.x < s) sm[threadIdx.x] |= sm[threadIdx.x + s];
            __syncthreads();
        }
        if (threadIdx.x == 0) g_anyodd = sm[0];
    }
}

__global__ void k_deg(const void* ei) {
    int e = blockIdx.x * blockDim.x + threadIdx.x;
    if (e >= NE) return;
    int is64 = (g_anyodd == 0);
    int c = ld_idx(ei, (long long)NE + e, is64);
    atomicAdd(&g_deg[c], 1);
}

// ---------------- 3-stage parallel scan of g_deg ----------------------------
__global__ void k_scanA() {
    __shared__ int sm[256];
    int t = threadIdx.x;
    int i = blockIdx.x * 256 + t;
    sm[t] = (i < NN) ? g_deg[i] : 0;
    __syncthreads();
    for (int s = 128; s > 0; s >>= 1) {
        if (t < s) sm[t] += sm[t + s];
        __syncthreads();
    }
    if (t == 0) g_bsum[blockIdx.x] = sm[0];
}

__global__ void k_scanB() {
    __shared__ int sm[256];
    int t = threadIdx.x;
    int v = (t < NB) ? g_bsum[t] : 0;
    sm[t] = v;
    __syncthreads();
    for (int off = 1; off < 256; off <<= 1) {
        int u = (t >= off) ? sm[t - off] : 0;
        __syncthreads();
        sm[t] += u;
        __syncthreads();
    }
    if (t < NB) g_boff[t] = sm[t] - v;   // exclusive
}

__global__ void k_scanC() {
    __shared__ int sm[256];
    int t = threadIdx.x;
    int i = blockIdx.x * 256 + t;
    int d = (i < NN) ? g_deg[i] : 0;
    sm[t] = d;
    __syncthreads();
    for (int off = 1; off < 256; off <<= 1) {
        int u = (t >= off) ? sm[t - off] : 0;
        __syncthreads();
        sm[t] += u;
        __syncthreads();
    }
    int off = g_boff[blockIdx.x] + sm[t] - d;   // exclusive prefix
    if (i < NN) {
        g_off[i] = off;
        g_cur[i] = off;
        g_dis[i] = rsqrtf((float)(d + 1));      // +1 self-loop
    }
    if (i == NN - 1) g_off[NN] = off + d;
}

__global__ void k_scatter(const void* ei) {
    int e = blockIdx.x * blockDim.x + threadIdx.x;
    if (e >= NE) return;
    int is64 = (g_anyodd == 0);
    int r = ld_idx(ei, e, is64);
    int c = ld_idx(ei, (long long)NE + e, is64);
    int pos = atomicAdd(&g_cur[c], 1);
    g_csr[pos] = r;
}

// ---------------- FFMA GEMM (R1 proven-best), bf16 output -------------------
// layer==0: A = x, stores RAW xw as bf16 (no dis -> no setup dependency).
// layer==1: A = g_buf1, stores dis*xw as bf16.
#define GM 64
__global__ void __launch_bounds__(256) k_gemm(const float* __restrict__ x_ext,
                                              const float* __restrict__ W,
                                              int layer) {
    __shared__ float Ws[32][DD];      // [k][n], rows 16B-aligned
    __shared__ float As[32][GM + 1];  // [k][m], padded
    const float* __restrict__ A = (layer == 0) ? x_ext : g_buf1;

    int t = threadIdx.x;
    int m0 = blockIdx.x * GM;
    int tr = t >> 5;   // 0..7  (8 row-groups)
    int tc = t & 31;   // 0..31 (32 col-groups of 4)

    float4 acc[8];
#pragma unroll
    for (int i = 0; i < 8; i++) acc[i] = make_float4(0.f, 0.f, 0.f, 0.f);

    for (int k0 = 0; k0 < DD; k0 += 32) {
        // load A tile [64 rows x 32 k] transposed into As[k][m]
#pragma unroll
        for (int q = 0; q < 2; q++) {
            int id = q * 256 + t;      // 0..511
            int r  = id >> 3;          // 0..63
            int kq = id & 7;           // 0..7 (float4 within row)
            int gm = m0 + r;
            float4 v = make_float4(0.f, 0.f, 0.f, 0.f);
            if (gm < NN) v = *(const float4*)&A[(size_t)gm * DD + k0 + kq * 4];
            As[kq * 4 + 0][r] = v.x;
            As[kq * 4 + 1][r] = v.y;
            As[kq * 4 + 2][r] = v.z;
            As[kq * 4 + 3][r] = v.w;
        }
        // load W tile [32 k x 128 n]
#pragma unroll
        for (int q = 0; q < 4; q++) {
            int id = q * 256 + t;      // 0..1023
            int kr = id >> 5;          // 0..31
            int cq = id & 31;          // 0..31
            *(float4*)&Ws[kr][cq * 4] =
                *(const float4*)&W[(size_t)(k0 + kr) * DD + cq * 4];
        }
        __syncthreads();

#pragma unroll
        for (int kk = 0; kk < 32; kk++) {
            float4 w = *(const float4*)&Ws[kk][tc * 4];
#pragma unroll
            for (int i = 0; i < 8; i++) {
                float a = As[kk][tr * 8 + i];
                acc[i].x += a * w.x;
                acc[i].y += a * w.y;
                acc[i].z += a * w.z;
                acc[i].w += a * w.w;
            }
        }
        __syncthreads();
    }

#pragma unroll
    for (int i = 0; i < 8; i++) {
        int gm = m0 + tr * 8 + i;
        if (gm < NN) {
            float ds = (layer == 0) ? 1.f : g_dis[gm];
            uint2 pk;
            pk.x = pack_bf(ds * acc[i].x, ds * acc[i].y);
            pk.y = pack_bf(ds * acc[i].z, ds * acc[i].w);
            *(uint2*)&g_bh[(size_t)gm * 64 + tc * 2] = pk;
        }
    }
}

// ---------------- aggregation (bf16 gathers, unroll-8 MLP) ------------------
// mode 0 (g_bh holds raw xw):  o = relu(dis[c]*(dis[c]*y[c] + sum dis[r]*y[r]) + b)
// mode 1 (g_bh holds dis*xw):  o = relu(dis[c]*(y[c] + sum y[r]) + b)
__global__ void __launch_bounds__(256) k_agg(const float* __restrict__ bias,
                                             int mode) {
    int w = (blockIdx.x * blockDim.x + threadIdx.x) >> 5;
    int lane = threadIdx.x & 31;
    if (w >= NN) return;
    float ds = g_dis[w];

    uint2 sv = *(const uint2*)&g_bh[(size_t)w * 64 + lane * 2];
    float2 s0 = unpack_bf(sv.x), s1 = unpack_bf(sv.y);
    float4 a0 = make_float4(s0.x, s0.y, s1.x, s1.y);   // self-loop term
    if (mode == 0) { a0.x *= ds; a0.y *= ds; a0.z *= ds; a0.w *= ds; }
    float4 a1 = make_float4(0.f, 0.f, 0.f, 0.f);
    float4 a2 = make_float4(0.f, 0.f, 0.f, 0.f);
    float4 a3 = make_float4(0.f, 0.f, 0.f, 0.f);

    int p = g_off[w];
    int e2 = g_off[w + 1];
    // unroll-8 main loop: 8 independent LDG.64 in flight per warp
    for (; p + 7 < e2; p += 8) {
        int rr[8];
#pragma unroll
        for (int j = 0; j < 8; j++) rr[j] = g_csr[p + j];
        uint2 uu[8];
#pragma unroll
        for (int j = 0; j < 8; j++)
            uu[j] = *(const uint2*)&g_bh[(size_t)rr[j] * 64 + lane * 2];
        if (mode == 0) {
            float dd[8];
#pragma unroll
            for (int j = 0; j < 8; j++) dd[j] = g_dis[rr[j]];
#pragma unroll
            for (int j = 0; j < 8; j++) {
                float2 fa = unpack_bf(uu[j].x), fb = unpack_bf(uu[j].y);
                float4* ac = (j & 3) == 0 ? &a0 : (j & 3) == 1 ? &a1
                           : (j & 3) == 2 ? &a2 : &a3;
                ac->x += dd[j] * fa.x; ac->y += dd[j] * fa.y;
                ac->z += dd[j] * fb.x; ac->w += dd[j] * fb.y;
            }
        } else {
#pragma unroll
            for (int j = 0; j < 8; j++) {
                float2 fa = unpack_bf(uu[j].x), fb = unpack_bf(uu[j].y);
                float4* ac = (j & 3) == 0 ? &a0 : (j & 3) == 1 ? &a1
                           : (j & 3) == 2 ? &a2 : &a3;
                ac->x += fa.x; ac->y += fa.y; ac->z += fb.x; ac->w += fb.y;
            }
        }
    }
    for (; p < e2; p++) {
        int r0 = g_csr[p];
        uint2 u0 = *(const uint2*)&g_bh[(size_t)r0 * 64 + lane * 2];
        float2 f0a = unpack_bf(u0.x), f0b = unpack_bf(u0.y);
        float d0 = (mode == 0) ? g_dis[r0] : 1.f;
        a0.x += d0 * f0a.x; a0.y += d0 * f0a.y;
        a0.z += d0 * f0b.x; a0.w += d0 * f0b.y;
    }
    float4 b = ((const float4*)bias)[lane];
    float4 o;
    o.x = fmaxf(ds * ((a0.x + a1.x) + (a2.x + a3.x)) + b.x, 0.f);
    o.y = fmaxf(ds * ((a0.y + a1.y) + (a2.y + a3.y)) + b.y, 0.f);
    o.z = fmaxf(ds * ((a0.z + a1.z) + (a2.z + a3.z)) + b.z, 0.f);
    o.w = fmaxf(ds * ((a0.w + a1.w) + (a2.w + a3.w)) + b.w, 0.f);
    ((float4*)g_buf1)[(size_t)w * 32 + lane] = o;
}

// ---------------- fused pool + FC + log_softmax (per-graph independent) -----
__global__ void k_poolhead(const void* batch,
                           const float* __restrict__ Wfc,
                           const float* __restrict__ bfc,
                           float* __restrict__ out) {
    __shared__ float red[4][DD];
    __shared__ float pool[DD];
    __shared__ float lg[NC];
    int g = blockIdx.x;
    int is64 = (g_anyodd == 0);
    int lo = 0, hi = NN;
    while (lo < hi) {
        int mid = (lo + hi) >> 1;
        if (ld_idx(batch, mid, is64) < g) lo = mid + 1; else hi = mid;
    }
    int start = lo;
    hi = NN;
    while (lo < hi) {
        int mid = (lo + hi) >> 1;
        if (ld_idx(batch, mid, is64) <= g) lo = mid + 1; else hi = mid;
    }
    int end = lo;

    int d = threadIdx.x & 127;
    int rg = threadIdx.x >> 7;   // 0..3
    const float* __restrict__ h = g_buf1;
    float s = 0.f;
    for (int i = start + rg; i < end; i += 4) s += h[(size_t)i * DD + d];
    red[rg][d] = s;
    __syncthreads();
    if (rg == 0) {
        float inv = 1.f / fmaxf((float)(end - start), 1.f);
        pool[d] = ((red[0][d] + red[1][d]) + (red[2][d] + red[3][d])) * inv;
    }
    __syncthreads();
    // FC: 10 logits, threads 0..9 each dot 128 dims
    if (threadIdx.x < NC) {
        int c = threadIdx.x;
        float acc = bfc[c];
#pragma unroll 4
        for (int dd2 = 0; dd2 < DD; dd2++)
            acc += pool[dd2] * Wfc[dd2 * NC + c];
        lg[c] = acc;
    }
    __syncthreads();
    if (threadIdx.x < NC) {
        int c = threadIdx.x;
        float m = -1e30f;
#pragma unroll
        for (int k = 0; k < NC; k++) m = fmaxf(m, lg[k]);
        float sum = 0.f;
#pragma unroll
        for (int k = 0; k < NC; k++) sum += expf(lg[k] - m);
        out[g * NC + c] = lg[c] - m - logf(sum);
    }
}

// ---------------- launch ----------------------------------------------------
extern "C" void kernel_launch(void* const* d_in, const int* in_sizes, int n_in,
                              void* d_out, int out_size) {
    (void)in_sizes; (void)n_in; (void)out_size;
    const float* x   = (const float*)d_in[0];
    const void*  ei  = d_in[1];
    const void*  bat = d_in[2];
    const float* W1  = (const float*)d_in[3];
    const float* b1  = (const float*)d_in[4];
    const float* W2  = (const float*)d_in[5];
    const float* b2  = (const float*)d_in[6];
    const float* Wfc = (const float*)d_in[7];
    const float* bfc = (const float*)d_in[8];
    float* out = (float*)d_out;

    // Side stream + events, created once on the (uncaptured) first call and
    // reused thereafter; the launched work is identical on every call.
    static cudaStream_t s2 = nullptr;
    static cudaEvent_t ev_fork = nullptr, ev_join = nullptr;
    if (s2 == nullptr) {
        cudaStreamCreateWithFlags(&s2, cudaStreamNonBlocking);
        cudaEventCreateWithFlags(&ev_fork, cudaEventDisableTiming);
        cudaEventCreateWithFlags(&ev_join, cudaEventDisableTiming);
    }

    int gblocks = (NN + GM - 1) / GM;   // 782

    // fork: GEMM1 (raw xw, no setup dependency) runs on s2 in parallel with
    // the CSR-build chain on the main stream.
    cudaEventRecord(ev_fork, 0);
    cudaStreamWaitEvent(s2, ev_fork, 0);
    k_gemm<<<gblocks, 256, 0, s2>>>(x, W1, 0);          // xw1 -> g_bh (raw)
    cudaEventRecord(ev_join, s2);

    k_init<<<NB, 256>>>(ei);
    k_deg<<<(NE + 255) / 256, 256>>>(ei);
    k_scanA<<<NB, 256>>>();
    k_scanB<<<1, 256>>>();
    k_scanC<<<NB, 256>>>();
    k_scatter<<<(NE + 255) / 256, 256>>>(ei);

    // join: agg1 needs CSR + dis (main stream) AND g_bh (s2)
    cudaStreamWaitEvent(0, ev_join, 0);

    k_agg<<<(NN * 32 + 255) / 256, 256>>>(b1, 0);       // h1 -> buf1
    k_gemm<<<gblocks, 256>>>(x, W2, 1);                 // dis*xw2 -> g_bh
    k_agg<<<(NN * 32 + 255) / 256, 256>>>(b2, 1);       // h2 -> buf1

    k_poolhead<<<NG, 512>>>(bat, Wfc, bfc, out);
}